// round 7
// baseline (speedup 1.0000x reference)
#include <cuda_runtime.h>
#include <cuda_fp16.h>
#include <math.h>

#define NN 8192
#define DD 256
#define HH 64

// Pre-scaled features: he[j, d] = e_j * h[j, d], fp16 (4 MB, L2-resident).
__device__ __half g_he[NN * DD];

// ---------------------------------------------------------------------------
// Kernel 1: e = sigmoid(relu(h @ W1 + b1) @ W2 + b2); emit he = e*h (fp16).
// 16 rows/block (512 blocks -> full 64-warp occupancy).
// j = tid&63, rg = tid>>6 owns 4 rows. h staged in smem (broadcast LDS.128);
// W1 untransposed, coalesced scalar LDG (L1-resident 64 KB).
// ---------------------------------------------------------------------------
#define MLP_ROWS 16
__global__ void __launch_bounds__(256) mlp_kernel(
    const float* __restrict__ h, const float* __restrict__ W1,
    const float* __restrict__ b1, const float* __restrict__ W2,
    const float* __restrict__ b2, float* __restrict__ out_e) {

  __shared__ __align__(16) float sh_h[MLP_ROWS * DD];   // 16 KB
  __shared__ float sT[MLP_ROWS][HH + 1];
  __shared__ float sE[MLP_ROWS];

  const int tid = threadIdx.x;
  const int rowbase = blockIdx.x * MLP_ROWS;

  // Stage 16 h rows, coalesced float4 (4 per thread).
  {
    const float4* src = (const float4*)(h + (size_t)rowbase * DD);
    float4* dst = (float4*)sh_h;
    #pragma unroll
    for (int i = tid; i < MLP_ROWS * DD / 4; i += 256) dst[i] = __ldg(&src[i]);
  }
  __syncthreads();

  const int j  = tid & 63;
  const int rg = tid >> 6;                  // 0..3, 4 rows each

  float acc[4];
  const float bj = __ldg(&b1[j]);
  #pragma unroll
  for (int r = 0; r < 4; r++) acc[r] = bj;

  const float4* sh4 = (const float4*)sh_h;

  #pragma unroll 4
  for (int k4 = 0; k4 < DD / 4; k4++) {
    const float w0 = __ldg(&W1[(k4 * 4 + 0) * HH + j]);
    const float w1 = __ldg(&W1[(k4 * 4 + 1) * HH + j]);
    const float w2 = __ldg(&W1[(k4 * 4 + 2) * HH + j]);
    const float w3 = __ldg(&W1[(k4 * 4 + 3) * HH + j]);
    #pragma unroll
    for (int r = 0; r < 4; r++) {
      const float4 hv = sh4[(rg * 4 + r) * (DD / 4) + k4];  // broadcast
      acc[r] = fmaf(hv.x, w0, fmaf(hv.y, w1, fmaf(hv.z, w2, fmaf(hv.w, w3, acc[r]))));
    }
  }

  {
    const float w2j = __ldg(&W2[j]);
    #pragma unroll
    for (int r = 0; r < 4; r++)
      sT[rg * 4 + r][j] = fmaxf(acc[r], 0.0f) * w2j;
  }
  __syncthreads();

  if (tid < MLP_ROWS) {
    float s = __ldg(&b2[0]);
    #pragma unroll
    for (int jj = 0; jj < HH; jj++) s += sT[tid][jj];
    const float ev = 1.0f / (1.0f + expf(-s));
    sE[tid] = ev;
    out_e[rowbase + tid] = ev;
  }
  __syncthreads();

  // Emit he16 = e_row * h from smem (4 float4 per thread).
  __half2* he2 = (__half2*)g_he;
  #pragma unroll
  for (int i = tid; i < MLP_ROWS * (DD / 4); i += 256) {
    const int r = i >> 6;
    const float4 hv = ((const float4*)sh_h)[i];
    const float e = sE[r];
    const size_t base = ((size_t)rowbase * DD + i * 4) >> 1;
    he2[base]     = __floats2half2_rn(hv.x * e, hv.y * e);
    he2[base + 1] = __floats2half2_rn(hv.z * e, hv.w * e);
  }
}

// ---------------------------------------------------------------------------
// Kernel 2: h_out[i,:] = sum_{j: A[i,j] > 0} he[j,:]
// One block (8 warps) per row.
//   scan:    8 front-batched __ldcs uint4 per thread -> register pending mask
//   compact: warp shfl-scan of popc(pending), ONE atomicAdd per warp, write
//            indices into block-shared list
//   gather:  BALANCED across warps (k = wid + 8i, unroll-2), fp16 he rows,
//            fp32 accumulate, cross-warp smem reduce (16B-aligned!).
// ---------------------------------------------------------------------------
__global__ void __launch_bounds__(256) agg_kernel(const float* __restrict__ A,
                                                  float* __restrict__ out) {
  __shared__ __align__(16) float s_red[8][DD];          // 8 KB, float4 stores
  __shared__ __align__(16) unsigned short s_idx[1024];
  __shared__ int s_cnt;

  const int row = blockIdx.x;
  const int tid = threadIdx.x;
  const int wid = tid >> 5;
  const int lane = tid & 31;

  if (tid == 0) s_cnt = 0;

  // Warp slice: 256 uint4 = 1024 columns starting at wid*1024.
  const uint4* Aslice = (const uint4*)(A + (size_t)row * NN) + wid * 256;

  // Front-batch all 8 streaming loads (DRAM MLP = 8).
  uint4 av[8];
  #pragma unroll
  for (int r = 0; r < 8; r++)
    av[r] = __ldcs(Aslice + r * 32 + lane);

  // pending bit (r*4 + c) = A[...] > 0 (a > 0 <=> bit pattern != 0).
  unsigned pending = 0u;
  #pragma unroll
  for (int r = 0; r < 8; r++) {
    unsigned f = 0u;
    if (av[r].x) f |= 1u;
    if (av[r].y) f |= 2u;
    if (av[r].z) f |= 4u;
    if (av[r].w) f |= 8u;
    pending |= f << (r * 4);
  }
  __syncthreads();   // s_cnt = 0 visible before any atomicAdd

  // Warp-aggregated compaction: shfl inclusive scan of per-lane counts.
  const int mycnt = __popc(pending);
  int incl = mycnt;
  #pragma unroll
  for (int off = 1; off < 32; off <<= 1) {
    const int n = __shfl_up_sync(0xFFFFFFFFu, incl, off);
    if (lane >= off) incl += n;
  }
  const int wtotal = __shfl_sync(0xFFFFFFFFu, incl, 31);
  int base = 0;
  if (lane == 31) base = atomicAdd(&s_cnt, wtotal);
  base = __shfl_sync(0xFFFFFFFFu, base, 31);

  {
    unsigned p = pending;
    int o = base + incl - mycnt;
    while (p) {
      const int b = __ffs(p) - 1;
      p &= p - 1u;
      const int j = wid * 1024 + ((b & ~3) << 5) + (lane << 2) + (b & 3);
      s_idx[o++] = (unsigned short)j;
    }
  }
  __syncthreads();
  const int cnt = s_cnt;

  // Balanced gather: warp w takes k = w, w+8, ... (unroll-2 for MLP).
  const uint4* he4 = (const uint4*)g_he;    // he row = 32 uint4 (256 halves)
  float acc[8] = {0.f, 0.f, 0.f, 0.f, 0.f, 0.f, 0.f, 0.f};

  int k = wid;
  for (; k + 8 < cnt; k += 16) {
    const int ja = s_idx[k];
    const int jb = s_idx[k + 8];
    const uint4 va = __ldg(&he4[(size_t)ja * 32 + lane]);
    const uint4 vb = __ldg(&he4[(size_t)jb * 32 + lane]);
    const __half2* pa = (const __half2*)&va;
    const __half2* pb = (const __half2*)&vb;
    #pragma unroll
    for (int q = 0; q < 4; q++) {
      const float2 fa = __half22float2(pa[q]);
      const float2 fb = __half22float2(pb[q]);
      acc[2 * q]     += fa.x + fb.x;
      acc[2 * q + 1] += fa.y + fb.y;
    }
  }
  if (k < cnt) {
    const int j = s_idx[k];
    const uint4 v = __ldg(&he4[(size_t)j * 32 + lane]);
    const __half2* p = (const __half2*)&v;
    #pragma unroll
    for (int q = 0; q < 4; q++) {
      const float2 f = __half22float2(p[q]);
      acc[2 * q]     += f.x;
      acc[2 * q + 1] += f.y;
    }
  }

  // Cross-warp reduce. acc[q] = column lane*8 + q. 16B-aligned float4 STS.
  {
    float4* rr = (float4*)s_red[wid];
    rr[lane * 2]     = make_float4(acc[0], acc[1], acc[2], acc[3]);
    rr[lane * 2 + 1] = make_float4(acc[4], acc[5], acc[6], acc[7]);
  }
  __syncthreads();

  float s = 0.0f;
  #pragma unroll
  for (int w = 0; w < 8; w++) s += s_red[w][tid];
  out[(size_t)row * DD + tid] = s;
}

// ---------------------------------------------------------------------------
// Inputs (setup_inputs order):
//   0: graph_info [N*N], 1: h [N*D], 2: W1 [D*H], 3: b1 [H], 4: W2 [H], 5: b2 [1]
// Output: h_out [N*D] followed by e [N].
// ---------------------------------------------------------------------------
extern "C" void kernel_launch(void* const* d_in, const int* in_sizes, int n_in,
                              void* d_out, int out_size) {
  const float* A  = (const float*)d_in[0];
  const float* h  = (const float*)d_in[1];
  const float* W1 = (const float*)d_in[2];
  const float* b1 = (const float*)d_in[3];
  const float* W2 = (const float*)d_in[4];
  const float* b2 = (const float*)d_in[5];

  float* out_h = (float*)d_out;                     // [N*D]
  float* out_e = (float*)d_out + (size_t)NN * DD;   // [N]

  mlp_kernel<<<NN / MLP_ROWS, 256>>>(h, W1, b1, W2, b2, out_e);
  agg_kernel<<<NN, 256>>>(A, out_h);
}